// round 12
// baseline (speedup 1.0000x reference)
#include <cuda_runtime.h>
#include <cuda_bf16.h>
#include <cstdint>

#define GW    2048
#define EMBD  32
#define HID   64
#define TPTS  256          // points per CTA
#define NTHR  256          // 8 warps
#define SA1   20           // u32 stride for K=32 tiles; (g*20+tq) residues cover all 32 banks
#define SA2   36           // u32 stride for K=64 tiles; (g*36+tq) residues cover all 32 banks
#define WREG  (64*SA2)     // per-warp activation region: 2304 u32 (H1 hi+lo)

// ---- SMEM offsets in 4-byte units ----
#define F_W3    0                     // 192 floats
#define F_B1    192
#define F_B2    256
#define F_B3    320
#define F_MU    324
#define F_STD   328
#define U_W1HI  352                   // 64*SA1 = 1280 u32
#define U_W1LO  (U_W1HI + 64*SA1)
#define U_W2HI  (U_W1LO + 64*SA1)     // 64*SA2 = 2304 u32
#define U_W2LO  (U_W2HI + 64*SA2)
#define U_POOL  (U_W2LO + 64*SA2)     // per-warp regions start here (multiple of 32)
#define SMEM_WORDS (U_POOL + 8*WREG)
#define SMEM_BYTES (SMEM_WORDS * 4)   // ~103.8 KB -> 2 CTAs/SM

typedef unsigned int u32;

__device__ __forceinline__ void split_bf(float v, __nv_bfloat16& hi, __nv_bfloat16& lo) {
    hi = __float2bfloat16_rn(v);
    lo = __float2bfloat16_rn(v - __bfloat162float(hi));
}
__device__ __forceinline__ u32 pack_bf2(__nv_bfloat16 lo16, __nv_bfloat16 hi16) {
    __nv_bfloat162 p = __nv_bfloat162(lo16, hi16);   // .x -> lower k
    return *(u32*)&p;
}

__device__ __forceinline__ void mma_bf16(float c[4], const u32 a[4], const u32 b[2]) {
    asm volatile(
        "mma.sync.aligned.m16n8k16.row.col.f32.bf16.bf16.f32 "
        "{%0,%1,%2,%3}, {%4,%5,%6,%7}, {%8,%9}, {%0,%1,%2,%3};"
        : "+f"(c[0]), "+f"(c[1]), "+f"(c[2]), "+f"(c[3])
        : "r"(a[0]), "r"(a[1]), "r"(a[2]), "r"(a[3]), "r"(b[0]), "r"(b[1]));
}

// One warp: its 32 rows x 64 cols. A is warp-local (Abase, row-local index),
// B shared weights. K = NK*16. 3 products: hh + hl + lh (lo*lo dropped).
template<int S, int NK>
__device__ __forceinline__ void warp_gemm_bf(
    const u32* __restrict__ Ahi, const u32* __restrict__ Alo,
    const u32* __restrict__ Bhi, const u32* __restrict__ Blo,
    float (&c)[2][8][4], int g, int tq)
{
    #pragma unroll
    for (int ks = 0; ks < NK; ks++) {
        const int k0 = ks * 8;
        u32 ah[2][4], al[2][4];
        #pragma unroll
        for (int mt = 0; mt < 2; mt++) {
            const int r0 = (mt * 16 + g) * S + k0 + tq;   // local rows
            const int r1 = r0 + 8 * S;
            ah[mt][0] = Ahi[r0];     ah[mt][1] = Ahi[r1];
            ah[mt][2] = Ahi[r0 + 4]; ah[mt][3] = Ahi[r1 + 4];
            al[mt][0] = Alo[r0];     al[mt][1] = Alo[r1];
            al[mt][2] = Alo[r0 + 4]; al[mt][3] = Alo[r1 + 4];
        }
        #pragma unroll
        for (int nt = 0; nt < 8; nt++) {
            const int nb = (nt * 8 + g) * S + k0 + tq;
            const u32 bh[2] = { Bhi[nb], Bhi[nb + 4] };
            const u32 bl[2] = { Blo[nb], Blo[nb + 4] };
            #pragma unroll
            for (int mt = 0; mt < 2; mt++) {
                mma_bf16(c[mt][nt], ah[mt], bh);
                mma_bf16(c[mt][nt], ah[mt], bl);
                mma_bf16(c[mt][nt], al[mt], bh);
            }
        }
    }
}

__global__ __launch_bounds__(NTHR)
void fused_bf16_kernel(
    const float* __restrict__ x, const float* __restrict__ positions,
    const int* __restrict__ nmap, const float* __restrict__ emb,
    const float* __restrict__ W1, const float* __restrict__ b1,
    const float* __restrict__ W2, const float* __restrict__ b2,
    const float* __restrict__ W3, const float* __restrict__ b3,
    const float* __restrict__ mu, const float* __restrict__ stdv,
    float* __restrict__ out, int n)
{
    extern __shared__ float sp[];
    u32* spu = (u32*)sp;
    const int t    = threadIdx.x;
    const int lane = t & 31;
    const int wid  = t >> 5;
    const int g    = lane >> 2;
    const int tq   = lane & 3;
    const int base = blockIdx.x * TPTS;
    const int i    = base + t;

    // per-warp activation region (LAT and H1 overlay each other warp-locally)
    u32* wb = spu + U_POOL + wid * WREG;
    u32* LATHI = wb;
    u32* LATLO = wb + 32 * SA1;
    u32* H1HI  = wb;
    u32* H1LO  = wb + 32 * SA2;

    // ---- kick off the dependent gather chain early (overlaps weight staging) ----
    float2 xy = make_float2(0.0f, 0.0f);
    if (i < n) xy = ((const float2*)x)[i];
    const int ix = (int)floorf(xy.x);
    const int iy = (int)floorf(xy.y);
    int4 nb4 = make_int4(0, 0, 0, 0);
    if (i < n) nb4 = ((const int4*)nmap)[ix * GW + iy];

    // ---- stage weights (CTA-shared) ----
    for (int idx = t; idx < 64 * 16; idx += NTHR) {        // W1 [64,32]
        const int no = idx >> 4, k2 = idx & 15;
        __nv_bfloat16 h0, l0, h1, l1;
        split_bf(W1[no * 32 + 2 * k2],     h0, l0);
        split_bf(W1[no * 32 + 2 * k2 + 1], h1, l1);
        spu[U_W1HI + no * SA1 + k2] = pack_bf2(h0, h1);
        spu[U_W1LO + no * SA1 + k2] = pack_bf2(l0, l1);
    }
    for (int idx = t; idx < 64 * 32; idx += NTHR) {        // W2 [64,64]
        const int no = idx >> 5, k2 = idx & 31;
        __nv_bfloat16 h0, l0, h1, l1;
        split_bf(W2[no * 64 + 2 * k2],     h0, l0);
        split_bf(W2[no * 64 + 2 * k2 + 1], h1, l1);
        spu[U_W2HI + no * SA2 + k2] = pack_bf2(h0, h1);
        spu[U_W2LO + no * SA2 + k2] = pack_bf2(l0, l1);
    }
    for (int idx = t; idx < 3 * HID; idx += NTHR) sp[F_W3 + idx] = W3[idx];
    if (t < HID) { sp[F_B1 + t] = b1[t]; sp[F_B2 + t] = b2[t]; }
    if (t < 3)   { sp[F_B3 + t] = b3[t]; sp[F_MU + t] = mu[t]; sp[F_STD + t] = stdv[t]; }

    // ---- finish gather: distance-weighted latent ----
    float lat[EMBD];
    #pragma unroll
    for (int d = 0; d < EMBD; d++) lat[d] = 0.0f;
    if (i < n) {
        const float fx = (float)ix, fy = (float)iy;
        const int nbk[4] = { nb4.x, nb4.y, nb4.z, nb4.w };
        #pragma unroll
        for (int k = 0; k < 4; k++) {
            const int idx = nbk[k];
            const float2 p = ((const float2*)positions)[idx];
            const float dx = p.x - fx, dy = p.y - fy;
            const float dist = sqrtf(dx * dx + dy * dy);
            const float4* e4 = (const float4*)(emb + (size_t)idx * EMBD);
            #pragma unroll
            for (int q = 0; q < EMBD / 4; q++) {
                const float4 e = e4[q];
                lat[4*q+0] = fmaf(dist, e.x, lat[4*q+0]);
                lat[4*q+1] = fmaf(dist, e.y, lat[4*q+1]);
                lat[4*q+2] = fmaf(dist, e.z, lat[4*q+2]);
                lat[4*q+3] = fmaf(dist, e.w, lat[4*q+3]);
            }
        }
    }

    // one CTA-wide sync: weights visible to everyone. After this, warps run free.
    __syncthreads();

    // store LAT (warp-local rows; lane = local row)
    #pragma unroll
    for (int k2 = 0; k2 < 16; k2++) {
        __nv_bfloat16 h0, l0, h1, l1;
        split_bf(lat[2 * k2],     h0, l0);
        split_bf(lat[2 * k2 + 1], h1, l1);
        LATHI[lane * SA1 + k2] = pack_bf2(h0, h1);
        LATLO[lane * SA1 + k2] = pack_bf2(l0, l1);
    }
    __syncwarp();

    // ---- GEMM1: D1 = LAT @ W1^T ----
    float c[2][8][4];
    #pragma unroll
    for (int mt = 0; mt < 2; mt++)
        #pragma unroll
        for (int nt = 0; nt < 8; nt++)
            #pragma unroll
            for (int e = 0; e < 4; e++) c[mt][nt][e] = 0.0f;

    warp_gemm_bf<SA1, 2>(LATHI, LATLO, &spu[U_W1HI], &spu[U_W1LO], c, g, tq);
    __syncwarp();   // all LAT reads done before H1 overlays this warp's region

    // ---- epilogue1: H1 = relu(D1 + b1) -> split bf16 -> packed store ----
    #pragma unroll
    for (int nt = 0; nt < 8; nt++) {
        const int c0 = nt * 8 + 2 * tq;
        const int kc = nt * 4 + tq;
        const float bc0 = sp[F_B1 + c0], bc1 = sp[F_B1 + c0 + 1];
        #pragma unroll
        for (int mt = 0; mt < 2; mt++) {
            const int r0 = mt * 16 + g, r1 = r0 + 8;   // local rows
            __nv_bfloat16 h0, l0, h1, l1;
            split_bf(fmaxf(c[mt][nt][0] + bc0, 0.0f), h0, l0);
            split_bf(fmaxf(c[mt][nt][1] + bc1, 0.0f), h1, l1);
            H1HI[r0 * SA2 + kc] = pack_bf2(h0, h1);
            H1LO[r0 * SA2 + kc] = pack_bf2(l0, l1);
            split_bf(fmaxf(c[mt][nt][2] + bc0, 0.0f), h0, l0);
            split_bf(fmaxf(c[mt][nt][3] + bc1, 0.0f), h1, l1);
            H1HI[r1 * SA2 + kc] = pack_bf2(h0, h1);
            H1LO[r1 * SA2 + kc] = pack_bf2(l0, l1);
        }
    }
    __syncwarp();

    // ---- GEMM2: D2 = H1 @ W2^T ----
    #pragma unroll
    for (int mt = 0; mt < 2; mt++)
        #pragma unroll
        for (int nt = 0; nt < 8; nt++)
            #pragma unroll
            for (int e = 0; e < 4; e++) c[mt][nt][e] = 0.0f;

    warp_gemm_bf<SA2, 4>(H1HI, H1LO, &spu[U_W2HI], &spu[U_W2LO], c, g, tq);

    // ---- epilogue2: relu + layer3 partials + quad reduce + output ----
    float a3[2][2][3];
    #pragma unroll
    for (int mt = 0; mt < 2; mt++)
        #pragma unroll
        for (int rh = 0; rh < 2; rh++)
            #pragma unroll
            for (int ch = 0; ch < 3; ch++) a3[mt][rh][ch] = 0.0f;

    #pragma unroll
    for (int nt = 0; nt < 8; nt++) {
        const int c0 = nt * 8 + 2 * tq;
        const float bc0 = sp[F_B2 + c0], bc1 = sp[F_B2 + c0 + 1];
        const float w30 = sp[F_W3 + 0*HID + c0], w31 = sp[F_W3 + 0*HID + c0 + 1];
        const float w40 = sp[F_W3 + 1*HID + c0], w41 = sp[F_W3 + 1*HID + c0 + 1];
        const float w50 = sp[F_W3 + 2*HID + c0], w51 = sp[F_W3 + 2*HID + c0 + 1];
        #pragma unroll
        for (int mt = 0; mt < 2; mt++) {
            const float h00 = fmaxf(c[mt][nt][0] + bc0, 0.0f);
            const float h01 = fmaxf(c[mt][nt][1] + bc1, 0.0f);
            const float h10 = fmaxf(c[mt][nt][2] + bc0, 0.0f);
            const float h11 = fmaxf(c[mt][nt][3] + bc1, 0.0f);
            a3[mt][0][0] = fmaf(h00, w30, fmaf(h01, w31, a3[mt][0][0]));
            a3[mt][0][1] = fmaf(h00, w40, fmaf(h01, w41, a3[mt][0][1]));
            a3[mt][0][2] = fmaf(h00, w50, fmaf(h01, w51, a3[mt][0][2]));
            a3[mt][1][0] = fmaf(h10, w30, fmaf(h11, w31, a3[mt][1][0]));
            a3[mt][1][1] = fmaf(h10, w40, fmaf(h11, w41, a3[mt][1][1]));
            a3[mt][1][2] = fmaf(h10, w50, fmaf(h11, w51, a3[mt][1][2]));
        }
    }
    #pragma unroll
    for (int mt = 0; mt < 2; mt++)
        #pragma unroll
        for (int rh = 0; rh < 2; rh++)
            #pragma unroll
            for (int ch = 0; ch < 3; ch++) {
                float v = a3[mt][rh][ch];
                v += __shfl_xor_sync(0xFFFFFFFFu, v, 1);
                v += __shfl_xor_sync(0xFFFFFFFFu, v, 2);
                a3[mt][rh][ch] = v;
            }

    if (tq == 0) {
        const float mu0 = sp[F_MU+0], mu1 = sp[F_MU+1], mu2 = sp[F_MU+2];
        const float sd0 = sp[F_STD+0], sd1 = sp[F_STD+1], sd2 = sp[F_STD+2];
        const float bb0 = sp[F_B3+0], bb1 = sp[F_B3+1], bb2 = sp[F_B3+2];
        #pragma unroll
        for (int mt = 0; mt < 2; mt++)
            #pragma unroll
            for (int rh = 0; rh < 2; rh++) {
                const int pi = base + wid * 32 + mt * 16 + rh * 8 + g;
                if (pi < n) {
                    const float o0 = (a3[mt][rh][0] + bb0) * sd0 + mu0;
                    const float o1 = (a3[mt][rh][1] + bb1) * sd1 + mu1;
                    const float o2 = (a3[mt][rh][2] + bb2) * sd2 + mu2;
                    const bool has_nan = (o0 != o0) || (o1 != o1) || (o2 != o2);
                    out[pi * 3 + 0] = has_nan ? mu0 : fminf(fmaxf(o0, 0.0f), 1.0f);
                    out[pi * 3 + 1] = has_nan ? mu1 : fminf(fmaxf(o1, 0.0f), 1.0f);
                    out[pi * 3 + 2] = has_nan ? mu2 : fminf(fmaxf(o2, 0.0f), 1.0f);
                }
            }
    }
}

extern "C" void kernel_launch(void* const* d_in, const int* in_sizes, int n_in,
                              void* d_out, int out_size) {
    const float* x    = (const float*)d_in[0];
    const float* pos  = (const float*)d_in[1];
    const int*   nmap = (const int*)d_in[2];
    const float* emb  = (const float*)d_in[3];
    const float* W1   = (const float*)d_in[4];
    const float* b1   = (const float*)d_in[5];
    const float* W2   = (const float*)d_in[6];
    const float* b2   = (const float*)d_in[7];
    const float* W3   = (const float*)d_in[8];
    const float* b3   = (const float*)d_in[9];
    const float* mu   = (const float*)d_in[10];
    const float* stdv = (const float*)d_in[11];
    float* out = (float*)d_out;

    const int n = in_sizes[0] / 2;
    const int grid = (n + TPTS - 1) / TPTS;
    cudaFuncSetAttribute(fused_bf16_kernel,
                         cudaFuncAttributeMaxDynamicSharedMemorySize, SMEM_BYTES);
    fused_bf16_kernel<<<grid, NTHR, SMEM_BYTES>>>(x, pos, nmap, emb, W1, b1, W2, b2,
                                                  W3, b3, mu, stdv, out, n);
}

// round 13
// speedup vs baseline: 1.0015x; 1.0015x over previous
#include <cuda_runtime.h>
#include <cuda_bf16.h>
#include <cstdint>

#define GW    2048
#define EMBD  32
#define HID   64
#define TPTS  256          // points per CTA
#define NTHR  256          // 8 warps
#define SA1   20           // u32 stride for K=32 tiles; (g*20+tq) residues cover all 32 banks
#define SA2   36           // u32 stride for K=64 tiles; (g*36+tq) residues cover all 32 banks
#define WREG  (64*SA2)     // per-warp activation region: 2304 u32 (H1 hi+lo)

// ---- SMEM offsets in 4-byte units ----
#define F_W3    0                     // 192 floats
#define F_B1    192
#define F_B2    256
#define F_B3    320
#define F_MU    324
#define F_STD   328
#define U_W1HI  352                   // 64*SA1 = 1280 u32
#define U_W1LO  (U_W1HI + 64*SA1)
#define U_W2HI  (U_W1LO + 64*SA1)     // 64*SA2 = 2304 u32
#define U_W2LO  (U_W2HI + 64*SA2)
#define U_POOL  (U_W2LO + 64*SA2)     // per-warp regions start here (multiple of 32)
#define SMEM_WORDS (U_POOL + 8*WREG)
#define SMEM_BYTES (SMEM_WORDS * 4)   // ~103.8 KB -> 2 CTAs/SM

typedef unsigned int u32;

__device__ __forceinline__ void split_bf(float v, __nv_bfloat16& hi, __nv_bfloat16& lo) {
    hi = __float2bfloat16_rn(v);
    lo = __float2bfloat16_rn(v - __bfloat162float(hi));
}
__device__ __forceinline__ u32 pack_bf2(__nv_bfloat16 lo16, __nv_bfloat16 hi16) {
    __nv_bfloat162 p = __nv_bfloat162(lo16, hi16);   // .x -> lower k
    return *(u32*)&p;
}

__device__ __forceinline__ void mma_bf16(float c[4], const u32 a[4], const u32 b[2]) {
    asm volatile(
        "mma.sync.aligned.m16n8k16.row.col.f32.bf16.bf16.f32 "
        "{%0,%1,%2,%3}, {%4,%5,%6,%7}, {%8,%9}, {%0,%1,%2,%3};"
        : "+f"(c[0]), "+f"(c[1]), "+f"(c[2]), "+f"(c[3])
        : "r"(a[0]), "r"(a[1]), "r"(a[2]), "r"(a[3]), "r"(b[0]), "r"(b[1]));
}

// One warp: its 32 rows x 64 cols. A is warp-local (Abase, row-local index),
// B shared weights. K = NK*16. 3 products: hh + hl + lh (lo*lo dropped).
template<int S, int NK>
__device__ __forceinline__ void warp_gemm_bf(
    const u32* __restrict__ Ahi, const u32* __restrict__ Alo,
    const u32* __restrict__ Bhi, const u32* __restrict__ Blo,
    float (&c)[2][8][4], int g, int tq)
{
    #pragma unroll
    for (int ks = 0; ks < NK; ks++) {
        const int k0 = ks * 8;
        u32 ah[2][4], al[2][4];
        #pragma unroll
        for (int mt = 0; mt < 2; mt++) {
            const int r0 = (mt * 16 + g) * S + k0 + tq;   // local rows
            const int r1 = r0 + 8 * S;
            ah[mt][0] = Ahi[r0];     ah[mt][1] = Ahi[r1];
            ah[mt][2] = Ahi[r0 + 4]; ah[mt][3] = Ahi[r1 + 4];
            al[mt][0] = Alo[r0];     al[mt][1] = Alo[r1];
            al[mt][2] = Alo[r0 + 4]; al[mt][3] = Alo[r1 + 4];
        }
        #pragma unroll
        for (int nt = 0; nt < 8; nt++) {
            const int nb = (nt * 8 + g) * S + k0 + tq;
            const u32 bh[2] = { Bhi[nb], Bhi[nb + 4] };
            const u32 bl[2] = { Blo[nb], Blo[nb + 4] };
            #pragma unroll
            for (int mt = 0; mt < 2; mt++) {
                mma_bf16(c[mt][nt], ah[mt], bh);
                mma_bf16(c[mt][nt], ah[mt], bl);
                mma_bf16(c[mt][nt], al[mt], bh);
            }
        }
    }
}

__global__ __launch_bounds__(NTHR)
void fused_bf16_kernel(
    const float* __restrict__ x, const float* __restrict__ positions,
    const int* __restrict__ nmap, const float* __restrict__ emb,
    const float* __restrict__ W1, const float* __restrict__ b1,
    const float* __restrict__ W2, const float* __restrict__ b2,
    const float* __restrict__ W3, const float* __restrict__ b3,
    const float* __restrict__ mu, const float* __restrict__ stdv,
    float* __restrict__ out, int n)
{
    extern __shared__ float sp[];
    u32* spu = (u32*)sp;
    const int t    = threadIdx.x;
    const int lane = t & 31;
    const int wid  = t >> 5;
    const int g    = lane >> 2;
    const int tq   = lane & 3;
    const int base = blockIdx.x * TPTS;
    const int i    = base + t;

    // per-warp activation region (LAT and H1 overlay each other warp-locally)
    u32* wb = spu + U_POOL + wid * WREG;
    u32* LATHI = wb;
    u32* LATLO = wb + 32 * SA1;
    u32* H1HI  = wb;
    u32* H1LO  = wb + 32 * SA2;

    // ---- kick off the dependent gather chain early (overlaps weight staging) ----
    float2 xy = make_float2(0.0f, 0.0f);
    if (i < n) xy = ((const float2*)x)[i];
    const int ix = (int)floorf(xy.x);
    const int iy = (int)floorf(xy.y);
    int4 nb4 = make_int4(0, 0, 0, 0);
    if (i < n) nb4 = ((const int4*)nmap)[ix * GW + iy];

    // ---- stage weights (CTA-shared) ----
    for (int idx = t; idx < 64 * 16; idx += NTHR) {        // W1 [64,32]
        const int no = idx >> 4, k2 = idx & 15;
        __nv_bfloat16 h0, l0, h1, l1;
        split_bf(W1[no * 32 + 2 * k2],     h0, l0);
        split_bf(W1[no * 32 + 2 * k2 + 1], h1, l1);
        spu[U_W1HI + no * SA1 + k2] = pack_bf2(h0, h1);
        spu[U_W1LO + no * SA1 + k2] = pack_bf2(l0, l1);
    }
    for (int idx = t; idx < 64 * 32; idx += NTHR) {        // W2 [64,64]
        const int no = idx >> 5, k2 = idx & 31;
        __nv_bfloat16 h0, l0, h1, l1;
        split_bf(W2[no * 64 + 2 * k2],     h0, l0);
        split_bf(W2[no * 64 + 2 * k2 + 1], h1, l1);
        spu[U_W2HI + no * SA2 + k2] = pack_bf2(h0, h1);
        spu[U_W2LO + no * SA2 + k2] = pack_bf2(l0, l1);
    }
    for (int idx = t; idx < 3 * HID; idx += NTHR) sp[F_W3 + idx] = W3[idx];
    if (t < HID) { sp[F_B1 + t] = b1[t]; sp[F_B2 + t] = b2[t]; }
    if (t < 3)   { sp[F_B3 + t] = b3[t]; sp[F_MU + t] = mu[t]; sp[F_STD + t] = stdv[t]; }

    // ---- finish gather: distance-weighted latent ----
    float lat[EMBD];
    #pragma unroll
    for (int d = 0; d < EMBD; d++) lat[d] = 0.0f;
    if (i < n) {
        const float fx = (float)ix, fy = (float)iy;
        const int nbk[4] = { nb4.x, nb4.y, nb4.z, nb4.w };
        #pragma unroll
        for (int k = 0; k < 4; k++) {
            const int idx = nbk[k];
            const float2 p = ((const float2*)positions)[idx];
            const float dx = p.x - fx, dy = p.y - fy;
            const float dist = sqrtf(dx * dx + dy * dy);
            const float4* e4 = (const float4*)(emb + (size_t)idx * EMBD);
            #pragma unroll
            for (int q = 0; q < EMBD / 4; q++) {
                const float4 e = e4[q];
                lat[4*q+0] = fmaf(dist, e.x, lat[4*q+0]);
                lat[4*q+1] = fmaf(dist, e.y, lat[4*q+1]);
                lat[4*q+2] = fmaf(dist, e.z, lat[4*q+2]);
                lat[4*q+3] = fmaf(dist, e.w, lat[4*q+3]);
            }
        }
    }

    // one CTA-wide sync: weights visible to everyone. After this, warps run free.
    __syncthreads();

    // store LAT (warp-local rows; lane = local row)
    #pragma unroll
    for (int k2 = 0; k2 < 16; k2++) {
        __nv_bfloat16 h0, l0, h1, l1;
        split_bf(lat[2 * k2],     h0, l0);
        split_bf(lat[2 * k2 + 1], h1, l1);
        LATHI[lane * SA1 + k2] = pack_bf2(h0, h1);
        LATLO[lane * SA1 + k2] = pack_bf2(l0, l1);
    }
    __syncwarp();

    // ---- GEMM1: D1 = LAT @ W1^T ----
    float c[2][8][4];
    #pragma unroll
    for (int mt = 0; mt < 2; mt++)
        #pragma unroll
        for (int nt = 0; nt < 8; nt++)
            #pragma unroll
            for (int e = 0; e < 4; e++) c[mt][nt][e] = 0.0f;

    warp_gemm_bf<SA1, 2>(LATHI, LATLO, &spu[U_W1HI], &spu[U_W1LO], c, g, tq);
    __syncwarp();   // all LAT reads done before H1 overlays this warp's region

    // ---- epilogue1: H1 = relu(D1 + b1) -> split bf16 -> packed store ----
    #pragma unroll
    for (int nt = 0; nt < 8; nt++) {
        const int c0 = nt * 8 + 2 * tq;
        const int kc = nt * 4 + tq;
        const float bc0 = sp[F_B1 + c0], bc1 = sp[F_B1 + c0 + 1];
        #pragma unroll
        for (int mt = 0; mt < 2; mt++) {
            const int r0 = mt * 16 + g, r1 = r0 + 8;   // local rows
            __nv_bfloat16 h0, l0, h1, l1;
            split_bf(fmaxf(c[mt][nt][0] + bc0, 0.0f), h0, l0);
            split_bf(fmaxf(c[mt][nt][1] + bc1, 0.0f), h1, l1);
            H1HI[r0 * SA2 + kc] = pack_bf2(h0, h1);
            H1LO[r0 * SA2 + kc] = pack_bf2(l0, l1);
            split_bf(fmaxf(c[mt][nt][2] + bc0, 0.0f), h0, l0);
            split_bf(fmaxf(c[mt][nt][3] + bc1, 0.0f), h1, l1);
            H1HI[r1 * SA2 + kc] = pack_bf2(h0, h1);
            H1LO[r1 * SA2 + kc] = pack_bf2(l0, l1);
        }
    }
    __syncwarp();

    // ---- GEMM2: D2 = H1 @ W2^T ----
    #pragma unroll
    for (int mt = 0; mt < 2; mt++)
        #pragma unroll
        for (int nt = 0; nt < 8; nt++)
            #pragma unroll
            for (int e = 0; e < 4; e++) c[mt][nt][e] = 0.0f;

    warp_gemm_bf<SA2, 4>(H1HI, H1LO, &spu[U_W2HI], &spu[U_W2LO], c, g, tq);

    // ---- epilogue2: relu + layer3 partials + quad reduce + output ----
    float a3[2][2][3];
    #pragma unroll
    for (int mt = 0; mt < 2; mt++)
        #pragma unroll
        for (int rh = 0; rh < 2; rh++)
            #pragma unroll
            for (int ch = 0; ch < 3; ch++) a3[mt][rh][ch] = 0.0f;

    #pragma unroll
    for (int nt = 0; nt < 8; nt++) {
        const int c0 = nt * 8 + 2 * tq;
        const float bc0 = sp[F_B2 + c0], bc1 = sp[F_B2 + c0 + 1];
        const float w30 = sp[F_W3 + 0*HID + c0], w31 = sp[F_W3 + 0*HID + c0 + 1];
        const float w40 = sp[F_W3 + 1*HID + c0], w41 = sp[F_W3 + 1*HID + c0 + 1];
        const float w50 = sp[F_W3 + 2*HID + c0], w51 = sp[F_W3 + 2*HID + c0 + 1];
        #pragma unroll
        for (int mt = 0; mt < 2; mt++) {
            const float h00 = fmaxf(c[mt][nt][0] + bc0, 0.0f);
            const float h01 = fmaxf(c[mt][nt][1] + bc1, 0.0f);
            const float h10 = fmaxf(c[mt][nt][2] + bc0, 0.0f);
            const float h11 = fmaxf(c[mt][nt][3] + bc1, 0.0f);
            a3[mt][0][0] = fmaf(h00, w30, fmaf(h01, w31, a3[mt][0][0]));
            a3[mt][0][1] = fmaf(h00, w40, fmaf(h01, w41, a3[mt][0][1]));
            a3[mt][0][2] = fmaf(h00, w50, fmaf(h01, w51, a3[mt][0][2]));
            a3[mt][1][0] = fmaf(h10, w30, fmaf(h11, w31, a3[mt][1][0]));
            a3[mt][1][1] = fmaf(h10, w40, fmaf(h11, w41, a3[mt][1][1]));
            a3[mt][1][2] = fmaf(h10, w50, fmaf(h11, w51, a3[mt][1][2]));
        }
    }
    #pragma unroll
    for (int mt = 0; mt < 2; mt++)
        #pragma unroll
        for (int rh = 0; rh < 2; rh++)
            #pragma unroll
            for (int ch = 0; ch < 3; ch++) {
                float v = a3[mt][rh][ch];
                v += __shfl_xor_sync(0xFFFFFFFFu, v, 1);
                v += __shfl_xor_sync(0xFFFFFFFFu, v, 2);
                a3[mt][rh][ch] = v;
            }

    if (tq == 0) {
        const float mu0 = sp[F_MU+0], mu1 = sp[F_MU+1], mu2 = sp[F_MU+2];
        const float sd0 = sp[F_STD+0], sd1 = sp[F_STD+1], sd2 = sp[F_STD+2];
        const float bb0 = sp[F_B3+0], bb1 = sp[F_B3+1], bb2 = sp[F_B3+2];
        #pragma unroll
        for (int mt = 0; mt < 2; mt++)
            #pragma unroll
            for (int rh = 0; rh < 2; rh++) {
                const int pi = base + wid * 32 + mt * 16 + rh * 8 + g;
                if (pi < n) {
                    const float o0 = (a3[mt][rh][0] + bb0) * sd0 + mu0;
                    const float o1 = (a3[mt][rh][1] + bb1) * sd1 + mu1;
                    const float o2 = (a3[mt][rh][2] + bb2) * sd2 + mu2;
                    const bool has_nan = (o0 != o0) || (o1 != o1) || (o2 != o2);
                    out[pi * 3 + 0] = has_nan ? mu0 : fminf(fmaxf(o0, 0.0f), 1.0f);
                    out[pi * 3 + 1] = has_nan ? mu1 : fminf(fmaxf(o1, 0.0f), 1.0f);
                    out[pi * 3 + 2] = has_nan ? mu2 : fminf(fmaxf(o2, 0.0f), 1.0f);
                }
            }
    }
}

extern "C" void kernel_launch(void* const* d_in, const int* in_sizes, int n_in,
                              void* d_out, int out_size) {
    const float* x    = (const float*)d_in[0];
    const float* pos  = (const float*)d_in[1];
    const int*   nmap = (const int*)d_in[2];
    const float* emb  = (const float*)d_in[3];
    const float* W1   = (const float*)d_in[4];
    const float* b1   = (const float*)d_in[5];
    const float* W2   = (const float*)d_in[6];
    const float* b2   = (const float*)d_in[7];
    const float* W3   = (const float*)d_in[8];
    const float* b3   = (const float*)d_in[9];
    const float* mu   = (const float*)d_in[10];
    const float* stdv = (const float*)d_in[11];
    float* out = (float*)d_out;

    const int n = in_sizes[0] / 2;
    const int grid = (n + TPTS - 1) / TPTS;
    cudaFuncSetAttribute(fused_bf16_kernel,
                         cudaFuncAttributeMaxDynamicSharedMemorySize, SMEM_BYTES);
    fused_bf16_kernel<<<grid, NTHR, SMEM_BYTES>>>(x, pos, nmap, emb, W1, b1, W2, b2,
                                                  W3, b3, mu, stdv, out, n);
}